// round 1
// baseline (speedup 1.0000x reference)
#include <cuda_runtime.h>
#include <math.h>
#include <stdint.h>

// Problem constants
#define BATCH 8
#define DIM   256
#define NSEQ  12306
#define NOUT  192   // TS^3 * 3

// Intermediate activations (device globals: allocation-free scratch)
__device__ float g_h1[BATCH * 512];
__device__ float g_h2[BATCH * 1024];
__device__ float g_h3[BATCH * 512];
__device__ float g_o [BATCH * NOUT];

// One kernel per layer: warp-per-neuron, all 8 batches per warp.
// X: [BATCH, K] contiguous. W: [Nout, K] row-major. Y: [BATCH, Nout].
// ACT: 0 = exact GELU, 1 = sigmoid.
template <int K, int ACT>
__global__ void layer_kernel(const float* __restrict__ X,
                             const float* __restrict__ W,
                             const float* __restrict__ bias,
                             float* __restrict__ Y,
                             int Nout)
{
    __shared__ float4 xs[BATCH][K / 4];

    // Stage all 8 batch activation vectors into shared memory (float4).
    const float4* X4 = reinterpret_cast<const float4*>(X);
    for (int i = threadIdx.x; i < BATCH * (K / 4); i += blockDim.x) {
        xs[i / (K / 4)][i % (K / 4)] = X4[i];
    }
    __syncthreads();

    const int warp = threadIdx.x >> 5;
    const int lane = threadIdx.x & 31;
    const int n = blockIdx.x * (blockDim.x >> 5) + warp;
    if (n >= Nout) return;

    const float4* wrow = reinterpret_cast<const float4*>(W + (size_t)n * K);

    float acc[BATCH];
#pragma unroll
    for (int b = 0; b < BATCH; b++) acc[b] = 0.0f;

#pragma unroll 4
    for (int i = lane; i < K / 4; i += 32) {
        float4 w4 = wrow[i];
#pragma unroll
        for (int b = 0; b < BATCH; b++) {
            float4 x4 = xs[b][i];
            acc[b] += w4.x * x4.x + w4.y * x4.y + w4.z * x4.z + w4.w * x4.w;
        }
    }

    // Butterfly warp reduction: after this, every lane holds full sums.
#pragma unroll
    for (int off = 16; off; off >>= 1) {
#pragma unroll
        for (int b = 0; b < BATCH; b++)
            acc[b] += __shfl_xor_sync(0xffffffffu, acc[b], off);
    }

    if (lane < BATCH) {
        float v = acc[lane] + bias[n];
        if (ACT == 0) {
            // exact GELU: 0.5 * v * (1 + erf(v / sqrt(2)))
            v = 0.5f * v * (1.0f + erff(v * 0.70710678118654752440f));
        } else {
            v = 1.0f / (1.0f + expf(-v));
        }
        Y[(size_t)lane * Nout + n] = v;
    }
}

// Broadcast: out[b].flat[f] = o[b, f / NSEQ].
// Each (b, out) pair owns a contiguous run of NSEQ floats -> one block per pair,
// pure value-fill with STG.128 in the aligned interior.
__global__ void bcast_kernel(float* __restrict__ out)
{
    const int p = blockIdx.x;            // 0 .. BATCH*NOUT-1
    const int b = p / NOUT;
    const int o = p % NOUT;
    const float val = g_o[p];

    float* dst = out + (size_t)b * NOUT * NSEQ + (size_t)o * NSEQ;

    // Align to 16B: runs start at 8B-misaligned offsets half the time
    const uintptr_t addr = (uintptr_t)dst;
    const int head = (int)(((16u - (addr & 15u)) & 15u) >> 2);   // floats until aligned
    const int t = threadIdx.x;

    if (t < head) dst[t] = val;

    const int rem = NSEQ - head;
    const int n4  = rem >> 2;
    float4* dst4 = reinterpret_cast<float4*>(dst + head);
    const float4 v4 = make_float4(val, val, val, val);

    for (int i = t; i < n4; i += blockDim.x) dst4[i] = v4;

    const int tail = rem & 3;
    if (t < tail) dst[head + (n4 << 2) + t] = val;
}

extern "C" void kernel_launch(void* const* d_in, const int* in_sizes, int n_in,
                              void* d_out, int out_size)
{
    const float* x  = (const float*)d_in[0];  // latent_x (8,1,256)
    const float* W1 = (const float*)d_in[1];
    const float* b1 = (const float*)d_in[2];
    const float* W2 = (const float*)d_in[3];
    const float* b2 = (const float*)d_in[4];
    const float* W3 = (const float*)d_in[5];
    const float* b3 = (const float*)d_in[6];
    const float* W4 = (const float*)d_in[7];
    const float* b4 = (const float*)d_in[8];
    float* out = (float*)d_out;

    float *h1, *h2, *h3, *o;
    cudaGetSymbolAddress((void**)&h1, g_h1);
    cudaGetSymbolAddress((void**)&h2, g_h2);
    cudaGetSymbolAddress((void**)&h3, g_h3);
    cudaGetSymbolAddress((void**)&o,  g_o);

    // 256 threads = 8 warps = 8 neurons/block
    layer_kernel<256,  0><<< 512 / 8, 256>>>(x,  W1, b1, h1, 512);
    layer_kernel<512,  0><<<1024 / 8, 256>>>(h1, W2, b2, h2, 1024);
    layer_kernel<1024, 0><<< 512 / 8, 256>>>(h2, W3, b3, h3, 512);
    layer_kernel<512,  1><<< NOUT / 8, 256>>>(h3, W4, b4, o, NOUT);

    bcast_kernel<<<BATCH * NOUT, 256>>>(out);
}

// round 2
// speedup vs baseline: 1.0010x; 1.0010x over previous
#include <cuda_runtime.h>
#include <math.h>
#include <stdint.h>

#define BATCH 8
#define NSEQ  12306
#define NOUT  192            // TS^3 * 3
#define NBLK  128
#define NTHR  256
#define NWARP (NTHR / 32)
#define PAIRS (BATCH * NOUT) // 1536
#define PPB   (PAIRS / NBLK) // 12 pairs per block
#define REG4  (PPB * NSEQ / 4) // 36918 float4 per block region (12*12306 divisible by 4)

// Device-global scratch (allocation-free)
__device__ float g_h1[BATCH * 512];
__device__ float g_h2[BATCH * 1024];
__device__ float g_h3[BATCH * 512];
__device__ float g_o [PAIRS];

// Grid barrier state. g_sense flips per barrier; 4 barriers per launch -> back to 0.
__device__ unsigned g_count = 0;
__device__ unsigned g_sense = 0;

__device__ __forceinline__ void gsync(unsigned& local_sense)
{
    __syncthreads();
    if (threadIdx.x == 0) {
        unsigned my = local_sense ^ 1u;
        local_sense = my;
        __threadfence();                       // publish this block's writes
        unsigned old = atomicAdd(&g_count, 1u);
        if (old == NBLK - 1) {
            g_count = 0;
            asm volatile("st.release.gpu.global.u32 [%0], %1;"
                         :: "l"(&g_sense), "r"(my) : "memory");
        } else {
            unsigned v;
            do {
                asm volatile("ld.acquire.gpu.global.u32 %0, [%1];"
                             : "=r"(v) : "l"(&g_sense) : "memory");
            } while (v != my);
        }
        __threadfence();
    }
    __syncthreads();
}

// Warp-per-neuron layer: X[BATCH,K] staged in smem, W[Nout,K] row-major.
// ACT 0 = exact GELU. Output Y[BATCH, Nout].
template <int K, int ACT>
__device__ __forceinline__ void do_layer(const float* __restrict__ X,
                                         const float* __restrict__ W,
                                         const float* __restrict__ bias,
                                         float* __restrict__ Y,
                                         int Nout, float4* xs4)
{
    const float4* X4 = reinterpret_cast<const float4*>(X);
    for (int i = threadIdx.x; i < BATCH * (K / 4); i += NTHR) xs4[i] = X4[i];
    __syncthreads();

    const int gw   = blockIdx.x * NWARP + (threadIdx.x >> 5);
    const int lane = threadIdx.x & 31;

    if (gw < Nout) {
        const float4* wrow = reinterpret_cast<const float4*>(W + (size_t)gw * K);
        float acc[BATCH];
#pragma unroll
        for (int b = 0; b < BATCH; b++) acc[b] = 0.0f;

#pragma unroll
        for (int i = lane; i < K / 4; i += 32) {
            float4 w4 = wrow[i];
#pragma unroll
            for (int b = 0; b < BATCH; b++) {
                float4 x4 = xs4[b * (K / 4) + i];
                acc[b] += w4.x * x4.x + w4.y * x4.y + w4.z * x4.z + w4.w * x4.w;
            }
        }
#pragma unroll
        for (int off = 16; off; off >>= 1)
#pragma unroll
            for (int b = 0; b < BATCH; b++)
                acc[b] += __shfl_xor_sync(0xffffffffu, acc[b], off);

        if (lane < BATCH) {
            float v = acc[lane] + bias[gw];
            if (ACT == 0)
                v = 0.5f * v * (1.0f + erff(v * 0.70710678118654752440f));
            else
                v = 1.0f / (1.0f + expf(-v));
            Y[(size_t)lane * Nout + gw] = v;
        }
    }
}

__global__ void __launch_bounds__(NTHR, 1)
fused_decoder_kernel(const float* __restrict__ x,
                     const float* __restrict__ W1, const float* __restrict__ b1,
                     const float* __restrict__ W2, const float* __restrict__ b2,
                     const float* __restrict__ W3, const float* __restrict__ b3,
                     const float* __restrict__ W4, const float* __restrict__ b4,
                     float* __restrict__ out)
{
    __shared__ float4 xs4[BATCH * 1024 / 4];   // 32 KB, reused per layer
    __shared__ float  svals[PPB];
    unsigned sense = 0;

    // ---- Layer 1: 256 -> 512, GELU ----
    do_layer<256, 0>(x, W1, b1, g_h1, 512, xs4);
    gsync(sense);

    // ---- Layer 2: 512 -> 1024, GELU ----
    do_layer<512, 0>(g_h1, W2, b2, g_h2, 1024, xs4);
    gsync(sense);

    // ---- Layer 3: 1024 -> 512, GELU ----
    do_layer<1024, 0>(g_h2, W3, b3, g_h3, 512, xs4);
    gsync(sense);

    // ---- Layer 4: 512 -> 192 per batch (1536 pairs), sigmoid ----
    {
        // stage h3 (8x512 = 16KB)
        const float4* H4 = reinterpret_cast<const float4*>(g_h3);
        for (int i = threadIdx.x; i < BATCH * 128; i += NTHR) xs4[i] = H4[i];
        __syncthreads();

        const int gw   = blockIdx.x * NWARP + (threadIdx.x >> 5);
        const int lane = threadIdx.x & 31;
#pragma unroll
        for (int rep = 0; rep < 2; rep++) {
            int p = gw + rep * (NBLK * NWARP);       // 0..1023, 1024..2047
            if (p < PAIRS) {
                int b = p / NOUT, o = p % NOUT;
                const float4* wrow = reinterpret_cast<const float4*>(W4 + (size_t)o * 512);
                float acc = 0.0f;
#pragma unroll
                for (int i = lane; i < 128; i += 32) {
                    float4 w4 = wrow[i];
                    float4 x4 = xs4[b * 128 + i];
                    acc += w4.x * x4.x + w4.y * x4.y + w4.z * x4.z + w4.w * x4.w;
                }
#pragma unroll
                for (int off = 16; off; off >>= 1)
                    acc += __shfl_xor_sync(0xffffffffu, acc, off);
                if (lane == 0) {
                    float v = acc + b4[o];
                    g_o[p] = 1.0f / (1.0f + expf(-v));
                }
            }
        }
    }
    gsync(sense);   // 4th barrier -> g_sense back to 0 for next replay

    // ---- Broadcast: out.flat[j] = g_o[j / NSEQ] ----
    // Block region: PPB contiguous pairs = REG4 float4, 16B-aligned.
    if (threadIdx.x < PPB) svals[threadIdx.x] = g_o[blockIdx.x * PPB + threadIdx.x];
    __syncthreads();

    float4* dst = reinterpret_cast<float4*>(out + (size_t)blockIdx.x * PPB * NSEQ);
    for (int q = threadIdx.x; q < REG4; q += NTHR) {
        int j = q << 2;                 // float offset within region
        int p = j / NSEQ;               // constant divide -> mul-hi
        int r = j - p * NSEQ;
        float4 v;
        if (r + 3 < NSEQ) {
            float f = svals[p];
            v = make_float4(f, f, f, f);
        } else {
            // float4 straddles a pair boundary (NSEQ % 4 == 2)
            float a = svals[p];
            float bnext = svals[p + 1 < PPB ? p + 1 : p]; // p+1 valid: straddle only inside region
            v.x = (r + 0 < NSEQ) ? a : bnext;
            v.y = (r + 1 < NSEQ) ? a : bnext;
            v.z = (r + 2 < NSEQ) ? a : bnext;
            v.w = (r + 3 < NSEQ) ? a : bnext;
        }
        dst[q] = v;
    }
}

extern "C" void kernel_launch(void* const* d_in, const int* in_sizes, int n_in,
                              void* d_out, int out_size)
{
    const float* x  = (const float*)d_in[0];
    const float* W1 = (const float*)d_in[1];
    const float* b1 = (const float*)d_in[2];
    const float* W2 = (const float*)d_in[3];
    const float* b2 = (const float*)d_in[4];
    const float* W3 = (const float*)d_in[5];
    const float* b3 = (const float*)d_in[6];
    const float* W4 = (const float*)d_in[7];
    const float* b4 = (const float*)d_in[8];

    fused_decoder_kernel<<<NBLK, NTHR>>>(x, W1, b1, W2, b2, W3, b3, W4, b4,
                                         (float*)d_out);
}

// round 3
// speedup vs baseline: 1.0612x; 1.0602x over previous
#include <cuda_runtime.h>
#include <math.h>
#include <stdint.h>

#define BATCH 8
#define NSEQ  12306
#define NOUT  192            // TS^3 * 3
#define NBLK  128
#define NTHR  1024
#define NWARP (NTHR / 32)    // 32
#define PAIRS (BATCH * NOUT) // 1536
#define PPB   (PAIRS / NBLK) // 12 pairs per block

// Device-global scratch (allocation-free)
__device__ float g_h1[BATCH * 512];
__device__ float g_h2[BATCH * 1024];
__device__ float g_h3[BATCH * 512];

// Grid barrier state (sense-reversing; starting sense is READ at kernel entry,
// so an odd number of barriers per launch is replay-safe).
__device__ unsigned g_count = 0;
__device__ unsigned g_sense = 0;

__device__ __forceinline__ void gsync(unsigned& local_sense)
{
    __syncthreads();
    if (threadIdx.x == 0) {
        unsigned my = local_sense ^ 1u;
        local_sense = my;
        __threadfence();                       // publish this block's writes
        unsigned old = atomicAdd(&g_count, 1u);
        if (old == NBLK - 1) {
            g_count = 0;
            asm volatile("st.release.gpu.global.u32 [%0], %1;"
                         :: "l"(&g_sense), "r"(my) : "memory");
        } else {
            unsigned v;
            do {
                asm volatile("ld.acquire.gpu.global.u32 %0, [%1];"
                             : "=r"(v) : "l"(&g_sense) : "memory");
            } while (v != my);
        }
        __threadfence();
    }
    __syncthreads();
}

// Warp-per-neuron layer. Neurons striped across blocks so every block has
// Nout/NBLK busy warps. X[BATCH,K] staged in smem. W[Nout,K] row-major.
template <int K, int ACT>
__device__ __forceinline__ void do_layer(const float* __restrict__ X,
                                         const float* __restrict__ W,
                                         const float* __restrict__ bias,
                                         float* __restrict__ Y,
                                         int Nout, float4* xs4)
{
    const float4* X4 = reinterpret_cast<const float4*>(X);
    for (int i = threadIdx.x; i < BATCH * (K / 4); i += NTHR) xs4[i] = X4[i];
    __syncthreads();

    const int wid  = threadIdx.x >> 5;
    const int lane = threadIdx.x & 31;
    const int n    = wid * NBLK + blockIdx.x;   // stripe neurons across blocks

    if (n < Nout) {
        const float4* wrow = reinterpret_cast<const float4*>(W + (size_t)n * K);
        float acc[BATCH];
#pragma unroll
        for (int b = 0; b < BATCH; b++) acc[b] = 0.0f;

#pragma unroll
        for (int i = lane; i < K / 4; i += 32) {
            float4 w4 = wrow[i];
#pragma unroll
            for (int b = 0; b < BATCH; b++) {
                float4 x4 = xs4[b * (K / 4) + i];
                acc[b] += w4.x * x4.x + w4.y * x4.y + w4.z * x4.z + w4.w * x4.w;
            }
        }
#pragma unroll
        for (int off = 16; off; off >>= 1)
#pragma unroll
            for (int b = 0; b < BATCH; b++)
                acc[b] += __shfl_xor_sync(0xffffffffu, acc[b], off);

        if (lane < BATCH) {
            float v = acc[lane] + bias[n];
            if (ACT == 0)
                v = 0.5f * v * (1.0f + erff(v * 0.70710678118654752440f));
            else
                v = 1.0f / (1.0f + expf(-v));
            Y[(size_t)lane * Nout + n] = v;
        }
    }
    __syncthreads();   // xs4 reused by next phase
}

__global__ void __launch_bounds__(NTHR, 1)
fused_decoder_kernel(const float* __restrict__ x,
                     const float* __restrict__ W1, const float* __restrict__ b1,
                     const float* __restrict__ W2, const float* __restrict__ b2,
                     const float* __restrict__ W3, const float* __restrict__ b3,
                     const float* __restrict__ W4, const float* __restrict__ b4,
                     float* __restrict__ out)
{
    __shared__ float4 xs4[BATCH * 1024 / 4];   // 32 KB, reused per layer
    __shared__ float  svals[PPB];

    unsigned sense = 0;
    if (threadIdx.x == 0)
        sense = *((volatile unsigned*)&g_sense);   // replay-safe starting sense

    // ---- Layers 1-3 (global, barrier-separated) ----
    do_layer<256,  0>(x,    W1, b1, g_h1, 512,  xs4);
    gsync(sense);
    do_layer<512,  0>(g_h1, W2, b2, g_h2, 1024, xs4);
    gsync(sense);
    do_layer<1024, 0>(g_h2, W3, b3, g_h3, 512,  xs4);
    gsync(sense);

    // ---- Layer 4: LOCAL. Each block computes only its own 12 (b,o) pairs ----
    {
        const float4* H4 = reinterpret_cast<const float4*>(g_h3);
        for (int i = threadIdx.x; i < BATCH * 128; i += NTHR) xs4[i] = H4[i];
        __syncthreads();

        const int wid  = threadIdx.x >> 5;
        const int lane = threadIdx.x & 31;
        if (wid < PPB) {
            const int p = blockIdx.x * PPB + wid;
            const int b = p / NOUT, o = p % NOUT;
            const float4* wrow = reinterpret_cast<const float4*>(W4 + (size_t)o * 512);
            float acc = 0.0f;
#pragma unroll
            for (int i = lane; i < 128; i += 32) {
                float4 w4 = wrow[i];
                float4 x4 = xs4[b * 128 + i];
                acc += w4.x * x4.x + w4.y * x4.y + w4.z * x4.z + w4.w * x4.w;
            }
#pragma unroll
            for (int off = 16; off; off >>= 1)
                acc += __shfl_xor_sync(0xffffffffu, acc, off);
            if (lane == 0) {
                float v = acc + b4[o];
                svals[wid] = 1.0f / (1.0f + expf(-v));
            }
        }
        __syncthreads();
    }

    // ---- Broadcast: pair p fills a contiguous run of NSEQ floats ----
    // Block region = PPB*NSEQ floats, 16B-aligned (PPB*NSEQ % 4 == 0).
    float* dst = out + (size_t)blockIdx.x * (PPB * NSEQ);
    float4* d4 = reinterpret_cast<float4*>(dst);
    const int t = threadIdx.x;

#pragma unroll
    for (int p = 0; p < PPB; p++) {
        const float v = svals[p];
        const int s    = p * NSEQ;              // pair start (float offset)
        const int h    = (4 - (s & 3)) & 3;     // scalar head (0 or 2)
        const int a0   = (s + h) >> 2;          // first full float4
        const int e    = s + NSEQ;
        const int e4   = e >> 2;                // exclusive end of full float4s
        const int tail = e & 3;                 // scalar tail (0 or 2)

        if (t < h)    dst[s + t] = v;
        if (t < tail) dst[(e4 << 2) + t] = v;

        const float4 v4 = make_float4(v, v, v, v);
        for (int i = a0 + t; i < e4; i += NTHR) d4[i] = v4;
    }
}

extern "C" void kernel_launch(void* const* d_in, const int* in_sizes, int n_in,
                              void* d_out, int out_size)
{
    const float* x  = (const float*)d_in[0];
    const float* W1 = (const float*)d_in[1];
    const float* b1 = (const float*)d_in[2];
    const float* W2 = (const float*)d_in[3];
    const float* b2 = (const float*)d_in[4];
    const float* W3 = (const float*)d_in[5];
    const float* b3 = (const float*)d_in[6];
    const float* W4 = (const float*)d_in[7];
    const float* b4 = (const float*)d_in[8];

    fused_decoder_kernel<<<NBLK, NTHR>>>(x, W1, b1, W2, b2, W3, b3, W4, b4,
                                         (float*)d_out);
}

// round 4
// speedup vs baseline: 1.1304x; 1.0652x over previous
#include <cuda_runtime.h>
#include <math.h>
#include <stdint.h>

#define BATCH 8
#define NSEQ  12306
#define NOUT  192             // TS^3 * 3
#define NBLK  128
#define NTHR  1024
#define PAIRS (BATCH * NOUT)  // 1536
#define PPB   (PAIRS / NBLK)  // 12 pairs per block
#define GBLK  16              // blocks per group (one group per batch)

// Per-batch activation scratch
__device__ float g_h1[BATCH][512];
__device__ float g_h2[BATCH][1024];
__device__ float g_h3[BATCH][512];

// Per-group sub-barrier state; count and sense on separate 128B lines.
__device__ unsigned g_count[BATCH][32];   // [g][0] used
__device__ unsigned g_sense[BATCH][32];   // [g][0] used

// 16-block sense-reversing sub-barrier (group g). Starting sense is read at
// kernel entry, so an odd barrier count per launch is replay-safe.
__device__ __forceinline__ void gsync(int g, unsigned& local_sense)
{
    __syncthreads();
    if (threadIdx.x == 0) {
        unsigned my = local_sense ^ 1u;
        local_sense = my;
        __threadfence();
        unsigned old = atomicAdd(&g_count[g][0], 1u);
        if (old == GBLK - 1) {
            g_count[g][0] = 0;
            asm volatile("st.release.gpu.global.u32 [%0], %1;"
                         :: "l"(&g_sense[g][0]), "r"(my) : "memory");
        } else {
            unsigned v;
            do {
                asm volatile("ld.acquire.gpu.global.u32 %0, [%1];"
                             : "=r"(v) : "l"(&g_sense[g][0]) : "memory");
            } while (v != my);
        }
        __threadfence();
    }
    __syncthreads();
}

// One dot product of length K against smem-staged x-row; warp-collective.
template <int K>
__device__ __forceinline__ float warp_dot(const float* __restrict__ W, int n,
                                          const float4* __restrict__ xs4, int lane)
{
    const float4* wrow = reinterpret_cast<const float4*>(W + (size_t)n * K);
    float acc = 0.0f;
#pragma unroll
    for (int i = lane; i < K / 4; i += 32) {
        float4 w4 = wrow[i];
        float4 x4 = xs4[i];
        acc += w4.x * x4.x + w4.y * x4.y + w4.z * x4.z + w4.w * x4.w;
    }
#pragma unroll
    for (int off = 16; off; off >>= 1)
        acc += __shfl_xor_sync(0xffffffffu, acc, off);
    return acc;
}

__device__ __forceinline__ float gelu_exact(float v)
{
    return 0.5f * v * (1.0f + erff(v * 0.70710678118654752440f));
}

template <int K>
__device__ __forceinline__ void stage_row(const float* __restrict__ src,
                                          float4* __restrict__ xs4)
{
    const float4* s4 = reinterpret_cast<const float4*>(src);
    for (int i = threadIdx.x; i < K / 4; i += NTHR) xs4[i] = s4[i];
    __syncthreads();
}

__global__ void __launch_bounds__(NTHR, 1)
fused_decoder_kernel(const float* __restrict__ x,
                     const float* __restrict__ W1, const float* __restrict__ b1,
                     const float* __restrict__ W2, const float* __restrict__ b2,
                     const float* __restrict__ W3, const float* __restrict__ b3,
                     const float* __restrict__ W4, const float* __restrict__ b4,
                     float* __restrict__ out)
{
    __shared__ float4 xs4[256];    // up to 1024 floats (4 KB), reused per layer
    __shared__ float  svals[PPB];

    const int bid  = blockIdx.x;
    const int g    = bid >> 4;                      // batch index 0..7
    const int wid  = threadIdx.x >> 5;
    const int lane = threadIdx.x & 31;
    const int gw   = ((bid & 15) << 5) | wid;       // group-warp id 0..511

    unsigned sense = 0;
    if (threadIdx.x == 0)
        sense = *((volatile unsigned*)&g_sense[g][0]);

    // ---- Layer 1: x[g] (256) -> h1[g] (512), GELU. Warp-per-neuron. ----
    stage_row<256>(x + (size_t)g * 256, xs4);
    {
        float acc = warp_dot<256>(W1, gw, xs4, lane);
        if (lane == 0) g_h1[g][gw] = gelu_exact(acc + b1[gw]);
    }
    gsync(g, sense);

    // ---- Layer 2: h1[g] (512) -> h2[g] (1024), GELU. 2 neurons/warp. ----
    __syncthreads();   // xs4 reuse
    stage_row<512>(g_h1[g], xs4);
    {
        const int n0 = gw, n1 = gw + 512;
        const float4* w0 = reinterpret_cast<const float4*>(W2 + (size_t)n0 * 512);
        const float4* w1 = reinterpret_cast<const float4*>(W2 + (size_t)n1 * 512);
        float a0 = 0.0f, a1 = 0.0f;
#pragma unroll
        for (int i = lane; i < 128; i += 32) {
            float4 x4 = xs4[i];
            float4 v0 = w0[i];
            float4 v1 = w1[i];
            a0 += v0.x * x4.x + v0.y * x4.y + v0.z * x4.z + v0.w * x4.w;
            a1 += v1.x * x4.x + v1.y * x4.y + v1.z * x4.z + v1.w * x4.w;
        }
#pragma unroll
        for (int off = 16; off; off >>= 1) {
            a0 += __shfl_xor_sync(0xffffffffu, a0, off);
            a1 += __shfl_xor_sync(0xffffffffu, a1, off);
        }
        if (lane == 0) {
            g_h2[g][n0] = gelu_exact(a0 + b2[n0]);
            g_h2[g][n1] = gelu_exact(a1 + b2[n1]);
        }
    }
    gsync(g, sense);

    // ---- Layer 3: h2[g] (1024) -> h3[g] (512), GELU. Warp-per-neuron. ----
    __syncthreads();
    stage_row<1024>(g_h2[g], xs4);
    {
        float acc = warp_dot<1024>(W3, gw, xs4, lane);
        if (lane == 0) g_h3[g][gw] = gelu_exact(acc + b3[gw]);
    }
    gsync(g, sense);

    // ---- Layer 4: h3[g] (512) -> this block's 12 outputs, sigmoid. ----
    __syncthreads();
    stage_row<512>(g_h3[g], xs4);
    if (wid < PPB) {
        const int o = (bid & 15) * PPB + wid;       // 0..191 within batch
        float acc = warp_dot<512>(W4, o, xs4, lane);
        if (lane == 0) {
            float v = acc + b4[o];
            svals[wid] = 1.0f / (1.0f + expf(-v));
        }
    }
    __syncthreads();

    // ---- Broadcast: pair p = bid*PPB + wid fills NSEQ contiguous floats ----
    float* dst = out + (size_t)bid * (PPB * NSEQ);  // region 16B-aligned
    float4* d4 = reinterpret_cast<float4*>(dst);
    const int t = threadIdx.x;

#pragma unroll
    for (int p = 0; p < PPB; p++) {
        const float v  = svals[p];
        const int s    = p * NSEQ;             // pair start (float offset)
        const int h    = (4 - (s & 3)) & 3;    // scalar head (0 or 2)
        const int a0   = (s + h) >> 2;         // first full float4
        const int e    = s + NSEQ;
        const int e4   = e >> 2;               // exclusive end of full float4s
        const int tail = e & 3;                // scalar tail (0 or 2)

        if (t < h)    dst[s + t] = v;
        if (t < tail) dst[(e4 << 2) + t] = v;

        const float4 v4 = make_float4(v, v, v, v);
        for (int i = a0 + t; i < e4; i += NTHR) d4[i] = v4;
    }
}

extern "C" void kernel_launch(void* const* d_in, const int* in_sizes, int n_in,
                              void* d_out, int out_size)
{
    const float* x  = (const float*)d_in[0];
    const float* W1 = (const float*)d_in[1];
    const float* b1 = (const float*)d_in[2];
    const float* W2 = (const float*)d_in[3];
    const float* b2 = (const float*)d_in[4];
    const float* W3 = (const float*)d_in[5];
    const float* b3 = (const float*)d_in[6];
    const float* W4 = (const float*)d_in[7];
    const float* b4 = (const float*)d_in[8];

    fused_decoder_kernel<<<NBLK, NTHR>>>(x, W1, b1, W2, b2, W3, b3, W4, b4,
                                         (float*)d_out);
}

// round 6
// speedup vs baseline: 1.1404x; 1.0088x over previous
#include <cuda_runtime.h>
#include <math.h>
#include <stdint.h>

#define BATCH 8
#define NSEQ  12306
#define NOUT  192             // TS^3 * 3
#define NBLK  128
#define NTHR  1024
#define PAIRS (BATCH * NOUT)  // 1536
#define PPB   (PAIRS / NBLK)  // 12 pairs per block
#define GBLK  16              // blocks per group (one group per batch)

// Per-batch activation scratch + final MLP outputs
__device__ float g_h1[BATCH][512];
__device__ float g_h2[BATCH][1024];
__device__ float g_h3[BATCH][512];
__device__ float g_o [PAIRS];

// Per-group sub-barrier state; count and sense on separate 128B lines.
__device__ unsigned g_count[BATCH][32];
__device__ unsigned g_sense[BATCH][32];

// 16-block sense-reversing sub-barrier. Starting sense read at kernel entry,
// so an odd barrier count per launch is replay-safe.
__device__ __forceinline__ void gsync(int g, unsigned& local_sense)
{
    __syncthreads();
    if (threadIdx.x == 0) {
        unsigned my = local_sense ^ 1u;
        local_sense = my;
        __threadfence();
        unsigned old = atomicAdd(&g_count[g][0], 1u);
        if (old == GBLK - 1) {
            g_count[g][0] = 0;
            asm volatile("st.release.gpu.global.u32 [%0], %1;"
                         :: "l"(&g_sense[g][0]), "r"(my) : "memory");
        } else {
            unsigned v;
            do {
                asm volatile("ld.acquire.gpu.global.u32 %0, [%1];"
                             : "=r"(v) : "l"(&g_sense[g][0]) : "memory");
            } while (v != my);
        }
        __threadfence();
    }
    __syncthreads();
}

template <int K>
__device__ __forceinline__ float warp_dot(const float* __restrict__ W, int n,
                                          const float4* __restrict__ xs4, int lane)
{
    const float4* wrow = reinterpret_cast<const float4*>(W + (size_t)n * K);
    float acc = 0.0f;
#pragma unroll
    for (int i = lane; i < K / 4; i += 32) {
        float4 w4 = wrow[i];
        float4 x4 = xs4[i];
        acc += w4.x * x4.x + w4.y * x4.y + w4.z * x4.z + w4.w * x4.w;
    }
#pragma unroll
    for (int off = 16; off; off >>= 1)
        acc += __shfl_xor_sync(0xffffffffu, acc, off);
    return acc;
}

__device__ __forceinline__ float gelu_exact(float v)
{
    return 0.5f * v * (1.0f + erff(v * 0.70710678118654752440f));
}

template <int K>
__device__ __forceinline__ void stage_row(const float* __restrict__ src,
                                          float4* __restrict__ xs4)
{
    const float4* s4 = reinterpret_cast<const float4*>(src);
    for (int i = threadIdx.x; i < K / 4; i += NTHR) xs4[i] = s4[i];
    __syncthreads();
}

// ---------------- Kernel 1: full MLP -> g_o[1536] ----------------
__global__ void __launch_bounds__(NTHR, 1)
mlp_kernel(const float* __restrict__ x,
           const float* __restrict__ W1, const float* __restrict__ b1,
           const float* __restrict__ W2, const float* __restrict__ b2,
           const float* __restrict__ W3, const float* __restrict__ b3,
           const float* __restrict__ W4, const float* __restrict__ b4)
{
    __shared__ float4 xs4[256];

    const int bid  = blockIdx.x;
    const int g    = bid >> 4;                   // batch 0..7
    const int wid  = threadIdx.x >> 5;
    const int lane = threadIdx.x & 31;
    const int gw   = ((bid & 15) << 5) | wid;    // group-warp id 0..511

    // --- Bulk L2 prefetch of ALL weights (one 128B line per thread) ---
    // W1: 4096 lines, W2: 16384, W3: 16384, W4: 3072  (total 39936 <= 131072 threads)
    {
        const int t = bid * NTHR + threadIdx.x;
        const float* pf = nullptr;
        if      (t < 4096)  pf = W1 + (size_t)t * 32;
        else if (t < 20480) pf = W2 + (size_t)(t - 4096)  * 32;
        else if (t < 36864) pf = W3 + (size_t)(t - 20480) * 32;
        else if (t < 39936) pf = W4 + (size_t)(t - 36864) * 32;
        if (pf) asm volatile("prefetch.global.L2 [%0];" :: "l"(pf));
    }

    unsigned sense = 0;
    if (threadIdx.x == 0)
        sense = *((volatile unsigned*)&g_sense[g][0]);

    // ---- Layer 1: x[g] (256) -> h1[g] (512), GELU. Warp-per-neuron. ----
    stage_row<256>(x + (size_t)g * 256, xs4);
    {
        float acc = warp_dot<256>(W1, gw, xs4, lane);
        if (lane == 0) g_h1[g][gw] = gelu_exact(acc + b1[gw]);
    }
    gsync(g, sense);

    // ---- Layer 2: h1[g] (512) -> h2[g] (1024), GELU. 2 neurons/warp. ----
    __syncthreads();
    stage_row<512>(g_h1[g], xs4);
    {
        const int n0 = gw, n1 = gw + 512;
        const float4* w0 = reinterpret_cast<const float4*>(W2 + (size_t)n0 * 512);
        const float4* w1 = reinterpret_cast<const float4*>(W2 + (size_t)n1 * 512);
        float a0 = 0.0f, a1 = 0.0f;
#pragma unroll
        for (int i = lane; i < 128; i += 32) {
            float4 x4 = xs4[i];
            float4 v0 = w0[i];
            float4 v1 = w1[i];
            a0 += v0.x * x4.x + v0.y * x4.y + v0.z * x4.z + v0.w * x4.w;
            a1 += v1.x * x4.x + v1.y * x4.y + v1.z * x4.z + v1.w * x4.w;
        }
#pragma unroll
        for (int off = 16; off; off >>= 1) {
            a0 += __shfl_xor_sync(0xffffffffu, a0, off);
            a1 += __shfl_xor_sync(0xffffffffu, a1, off);
        }
        if (lane == 0) {
            g_h2[g][n0] = gelu_exact(a0 + b2[n0]);
            g_h2[g][n1] = gelu_exact(a1 + b2[n1]);
        }
    }
    gsync(g, sense);

    // ---- Layer 3: h2[g] (1024) -> h3[g] (512), GELU. Warp-per-neuron. ----
    __syncthreads();
    stage_row<1024>(g_h2[g], xs4);
    {
        float acc = warp_dot<1024>(W3, gw, xs4, lane);
        if (lane == 0) g_h3[g][gw] = gelu_exact(acc + b3[gw]);
    }
    gsync(g, sense);

    // ---- Layer 4: h3[g] (512) -> this block's 12 outputs, sigmoid. ----
    __syncthreads();
    stage_row<512>(g_h3[g], xs4);
    if (wid < PPB) {
        const int o = (bid & 15) * PPB + wid;      // 0..191 within batch
        float acc = warp_dot<512>(W4, o, xs4, lane);
        if (lane == 0)
            g_o[bid * PPB + wid] = 1.0f / (1.0f + expf(-(acc + b4[o])));
    }
}

// ---------------- Kernel 2: broadcast g_o -> out ----------------
// One block per (b,o) pair: fill NSEQ contiguous floats with one value.
__global__ void __launch_bounds__(256, 8)
bcast_kernel(float* __restrict__ out)
{
    const int p   = blockIdx.x;                  // 0..1535
    const float v = g_o[p];
    const int t   = threadIdx.x;

    float* dst = out + (size_t)p * NSEQ;
    const uintptr_t addr = (uintptr_t)dst;
    const int h = (int)(((16u - (addr & 15u)) & 15u) >> 2);   // head floats (0 or 2)

    if (t < h) dst[t] = v;

    const int rem  = NSEQ - h;
    const int n4   = rem >> 2;
    const int tail = rem & 3;

    if (t < tail) dst[h + (n4 << 2) + t] = v;

    float4* d4 = reinterpret_cast<float4*>(dst + h);
    const float4 v4 = make_float4(v, v, v, v);
    for (int i = t; i < n4; i += 256) d4[i] = v4;
}

extern "C" void kernel_launch(void* const* d_in, const int* in_sizes, int n_in,
                              void* d_out, int out_size)
{
    const float* x  = (const float*)d_in[0];
    const float* W1 = (const float*)d_in[1];
    const float* b1 = (const float*)d_in[2];
    const float* W2 = (const float*)d_in[3];
    const float* b2 = (const float*)d_in[4];
    const float* W3 = (const float*)d_in[5];
    const float* b3 = (const float*)d_in[6];
    const float* W4 = (const float*)d_in[7];
    const float* b4 = (const float*)d_in[8];

    mlp_kernel<<<NBLK, NTHR>>>(x, W1, b1, W2, b2, W3, b3, W4, b4);
    bcast_kernel<<<PAIRS, 256>>>((float*)d_out);
}

// round 7
// speedup vs baseline: 1.2279x; 1.0767x over previous
#include <cuda_runtime.h>
#include <math.h>
#include <stdint.h>

#define BATCH 8
#define NSEQ  12306
#define NOUT  192                 // TS^3 * 3
#define PAIRS (BATCH * NOUT)      // 1536
#define CSIZE 8                   // cluster size = blocks per batch
#define MLP_BLOCKS (BATCH * CSIZE)   // 64
#define MLP_THR    1024

#define BC_BLOCKS 592             // 148 SMs * 4 blocks  (exactly one wave)
#define BC_THR    512
#define NQ4 4725504               // 1536*12306/4 float4 in output

// Final MLP outputs (read by bcast kernel; kernel boundary orders memory)
__device__ float g_o[PAIRS];

// ---------- helpers ----------
__device__ __forceinline__ uint32_t smem_u32(const void* p)
{
    uint32_t a;
    asm("{ .reg .u64 t; cvta.to.shared.u64 t, %1; cvt.u32.u64 %0, t; }"
        : "=r"(a) : "l"(p));
    return a;
}

// Store {a,b} to B[ofs] of CTA `rank` in this cluster.
__device__ __forceinline__ void dsmem_st64(uint32_t laddr, uint32_t rank,
                                           float a, float b)
{
    uint64_t v;
    asm("mov.b64 %0, {%1, %2};" : "=l"(v) : "f"(a), "f"(b));
    asm volatile("{ .reg .b32 r; mapa.shared::cluster.u32 r, %0, %1; "
                 "st.shared::cluster.b64 [r], %2; }"
                 :: "r"(laddr), "r"(rank), "l"(v) : "memory");
}

__device__ __forceinline__ void csync()
{
    asm volatile("barrier.cluster.arrive.aligned;" ::: "memory");
    asm volatile("barrier.cluster.wait.aligned;"   ::: "memory");
}

__device__ __forceinline__ float gelu_exact(float v)
{
    return 0.5f * v * (1.0f + erff(v * 0.70710678118654752440f));
}

// NPW neuron dot products of length K against smem row `in`; warp-collective.
template <int K, int NPW>
__device__ __forceinline__ void warp_dotN(const float* __restrict__ in,
                                          const float* __restrict__ W,
                                          int n0, int lane, float* acc)
{
    const float4* in4 = reinterpret_cast<const float4*>(in);
    const float4* wr[NPW];
#pragma unroll
    for (int j = 0; j < NPW; j++) {
        acc[j] = 0.0f;
        wr[j]  = reinterpret_cast<const float4*>(W + (size_t)(n0 + j) * K);
    }
#pragma unroll
    for (int i = lane; i < K / 4; i += 32) {
        float4 x4 = in4[i];
#pragma unroll
        for (int j = 0; j < NPW; j++) {
            float4 w4 = wr[j][i];
            acc[j] += w4.x * x4.x + w4.y * x4.y + w4.z * x4.z + w4.w * x4.w;
        }
    }
#pragma unroll
    for (int off = 16; off; off >>= 1)
#pragma unroll
        for (int j = 0; j < NPW; j++)
            acc[j] += __shfl_xor_sync(0xffffffffu, acc[j], off);
}

// ---------------- Kernel 1: MLP (one 8-CTA cluster per batch) ----------------
__global__ void __launch_bounds__(MLP_THR, 1) __cluster_dims__(CSIZE, 1, 1)
mlp_kernel(const float* __restrict__ x,
           const float* __restrict__ W1, const float* __restrict__ b1,
           const float* __restrict__ W2, const float* __restrict__ b2,
           const float* __restrict__ W3, const float* __restrict__ b3,
           const float* __restrict__ W4, const float* __restrict__ b4)
{
    __shared__ float A[1024];   // layer inputs (x, h2)
    __shared__ float B[1024];   // layer inputs (h1, h3)

    const int bid   = blockIdx.x;
    const int g     = bid / CSIZE;          // batch 0..7
    const uint32_t rank = bid % CSIZE;      // == cluster ctarank (1D launch)
    const int wid   = threadIdx.x >> 5;
    const int lane  = threadIdx.x & 31;

    // Bulk L2 prefetch of all weights (one 128B line per thread; 39936 lines)
    {
        const int t = bid * MLP_THR + threadIdx.x;
        const float* pf = nullptr;
        if      (t < 4096)  pf = W1 + (size_t)t * 32;
        else if (t < 20480) pf = W2 + (size_t)(t - 4096)  * 32;
        else if (t < 36864) pf = W3 + (size_t)(t - 20480) * 32;
        else if (t < 39936) pf = W4 + (size_t)(t - 36864) * 32;
        if (pf) asm volatile("prefetch.global.L2 [%0];" :: "l"(pf));
    }

    const uint32_t Aaddr = smem_u32(A);
    const uint32_t Baddr = smem_u32(B);

    // Stage x[g] (256 floats) locally into A.
    if (threadIdx.x < 64)
        reinterpret_cast<float4*>(A)[threadIdx.x] =
            reinterpret_cast<const float4*>(x + (size_t)g * 256)[threadIdx.x];
    __syncthreads();

    // ---- L1: A(256) -> 512, GELU. 2 neurons/warp -> B (replicated) ----
    {
        const int n = (int)rank * 64 + wid * 2;
        float acc[2];
        warp_dotN<256, 2>(A, W1, n, lane, acc);
        if (lane == 0) {
            float v0 = gelu_exact(acc[0] + b1[n]);
            float v1 = gelu_exact(acc[1] + b1[n + 1]);
#pragma unroll
            for (uint32_t r = 0; r < CSIZE; r++)
                dsmem_st64(Baddr + n * 4u, r, v0, v1);
        }
    }
    csync();

    // ---- L2: B(512) -> 1024, GELU. 4 neurons/warp -> A (replicated) ----
    {
        const int n = (int)rank * 128 + wid * 4;
        float acc[4];
        warp_dotN<512, 4>(B, W2, n, lane, acc);
        if (lane == 0) {
            float v0 = gelu_exact(acc[0] + b2[n]);
            float v1 = gelu_exact(acc[1] + b2[n + 1]);
            float v2 = gelu_exact(acc[2] + b2[n + 2]);
            float v3 = gelu_exact(acc[3] + b2[n + 3]);
#pragma unroll
            for (uint32_t r = 0; r < CSIZE; r++) {
                dsmem_st64(Aaddr + n * 4u,     r, v0, v1);
                dsmem_st64(Aaddr + n * 4u + 8, r, v2, v3);
            }
        }
    }
    csync();

    // ---- L3: A(1024) -> 512, GELU. 2 neurons/warp -> B (replicated) ----
    {
        const int n = (int)rank * 64 + wid * 2;
        float acc[2];
        warp_dotN<1024, 2>(A, W3, n, lane, acc);
        if (lane == 0) {
            float v0 = gelu_exact(acc[0] + b3[n]);
            float v1 = gelu_exact(acc[1] + b3[n + 1]);
#pragma unroll
            for (uint32_t r = 0; r < CSIZE; r++)
                dsmem_st64(Baddr + n * 4u, r, v0, v1);
        }
    }
    csync();

    // ---- L4: B(512) -> 24 outputs/block, sigmoid -> g_o ----
    if (wid < 24) {
        const int o = (int)rank * 24 + wid;     // 0..191
        float acc[1];
        warp_dotN<512, 1>(B, W4, o, lane, acc);
        if (lane == 0)
            g_o[g * NOUT + o] = 1.0f / (1.0f + expf(-(acc[0] + b4[o])));
    }
}

// ---------------- Kernel 2: broadcast (one exact wave, flat stride) ----------
// out.flat[j] = g_o[j / NSEQ].  Iterate float4s; NSEQ % 4 == 2 so a float4
// straddles a pair boundary iff r == NSEQ-2.
__global__ void __launch_bounds__(BC_THR, 4)
bcast_kernel(float* __restrict__ out)
{
    float4* o4 = reinterpret_cast<float4*>(out);
    const unsigned stride = BC_BLOCKS * BC_THR;

    for (unsigned q = blockIdx.x * BC_THR + threadIdx.x; q < NQ4; q += stride) {
        const unsigned j = q << 2;
        const unsigned p = j / NSEQ;            // const-divide -> mulhi chain
        const unsigned r = j - p * NSEQ;
        const float a = __ldg(&g_o[p]);
        float4 v;
        if (r == NSEQ - 2) {                    // rare straddle (a,a,b,b)
            const float b = __ldg(&g_o[p + 1]);
            v = make_float4(a, a, b, b);
        } else {
            v = make_float4(a, a, a, a);
        }
        o4[q] = v;
    }
}

extern "C" void kernel_launch(void* const* d_in, const int* in_sizes, int n_in,
                              void* d_out, int out_size)
{
    const float* x  = (const float*)d_in[0];
    const float* W1 = (const float*)d_in[1];
    const float* b1 = (const float*)d_in[2];
    const float* W2 = (const float*)d_in[3];
    const float* b2 = (const float*)d_in[4];
    const float* W3 = (const float*)d_in[5];
    const float* b3 = (const float*)d_in[6];
    const float* W4 = (const float*)d_in[7];
    const float* b4 = (const float*)d_in[8];

    mlp_kernel<<<MLP_BLOCKS, MLP_THR>>>(x, W1, b1, W2, b2, W3, b3, W4, b4);
    bcast_kernel<<<BC_BLOCKS, BC_THR>>>((float*)d_out);
}